// round 3
// baseline (speedup 1.0000x reference)
#include <cuda_runtime.h>
#include <cstdint>
#include <climits>

#define BATCH 8192
#define DIN   768
#define DH    16384
#define TK    32
#define NCAND 40

// ---- scratch (static device globals; no dynamic allocation) ----
__device__ float g_z[(size_t)BATCH * DH];        // 512 MB post-relu activations
__device__ float g_wdt[(size_t)DH * DIN];        // 48 MB transposed W_dec
__device__ float g_candv[BATCH * NCAND];         // fp32 candidate values
__device__ int   g_candi[BATCH * NCAND];         // candidate indices
__device__ float g_selv[BATCH * TK];             // final selected values (fp32 z)
__device__ int   g_seli[BATCH * TK];             // final selected indices (ascending)

// ======================================================================
// Kernel 1: transpose W_dec [DIN, DH] -> g_wdt [DH, DIN]
// ======================================================================
__global__ void transpose_wdec(const float* __restrict__ wdec) {
    __shared__ float tile[32][33];
    const int h0 = blockIdx.x * 32;
    const int i0 = blockIdx.y * 32;
#pragma unroll
    for (int j = 0; j < 32; j += 8) {
        tile[threadIdx.y + j][threadIdx.x] =
            wdec[(size_t)(i0 + threadIdx.y + j) * DH + (h0 + threadIdx.x)];
    }
    __syncthreads();
#pragma unroll
    for (int j = 0; j < 32; j += 8) {
        g_wdt[(size_t)(h0 + threadIdx.y + j) * DIN + (i0 + threadIdx.x)] =
            tile[threadIdx.x][threadIdx.y + j];
    }
}

// ======================================================================
// Kernel 2: encode GEMM  z = relu(x @ W_enc^T + b_enc), exact fp32
// BM=BN=128, BK=16, 256 threads, 8x8 microtile, serial-k fp32 accumulate.
// ======================================================================
__global__ __launch_bounds__(256, 2)
void encode_kernel(const float* __restrict__ X, const float* __restrict__ W,
                   const float* __restrict__ benc) {
    const int bm = blockIdx.y * 128;
    const int bn = blockIdx.x * 128;

    __shared__ float As[16][128];   // As[k][m]
    __shared__ float Bs[16][128];   // Bs[k][n]

    const int tid = threadIdx.x;
    const int tx = tid & 15;
    const int ty = tid >> 4;

    const int s0 = tid * 2;
    const int r0 = s0 >> 2;
    const int c0 = (s0 & 3) * 4;
    const int r1 = (s0 + 1) >> 2;
    const int c1 = ((s0 + 1) & 3) * 4;

    float acc[8][8];
#pragma unroll
    for (int i = 0; i < 8; i++)
#pragma unroll
        for (int j = 0; j < 8; j++) acc[i][j] = 0.f;

    for (int k0 = 0; k0 < DIN; k0 += 16) {
        const float4 a0 = *(const float4*)&X[(size_t)(bm + r0) * DIN + k0 + c0];
        const float4 a1 = *(const float4*)&X[(size_t)(bm + r1) * DIN + k0 + c1];
        const float4 b0 = *(const float4*)&W[(size_t)(bn + r0) * DIN + k0 + c0];
        const float4 b1 = *(const float4*)&W[(size_t)(bn + r1) * DIN + k0 + c1];

        __syncthreads();
        As[c0 + 0][r0] = a0.x; As[c0 + 1][r0] = a0.y; As[c0 + 2][r0] = a0.z; As[c0 + 3][r0] = a0.w;
        As[c1 + 0][r1] = a1.x; As[c1 + 1][r1] = a1.y; As[c1 + 2][r1] = a1.z; As[c1 + 3][r1] = a1.w;
        Bs[c0 + 0][r0] = b0.x; Bs[c0 + 1][r0] = b0.y; Bs[c0 + 2][r0] = b0.z; Bs[c0 + 3][r0] = b0.w;
        Bs[c1 + 0][r1] = b1.x; Bs[c1 + 1][r1] = b1.y; Bs[c1 + 2][r1] = b1.z; Bs[c1 + 3][r1] = b1.w;
        __syncthreads();

#pragma unroll
        for (int kk = 0; kk < 16; kk++) {
            float a[8], b[8];
            *(float4*)&a[0] = *(const float4*)&As[kk][ty * 8];
            *(float4*)&a[4] = *(const float4*)&As[kk][ty * 8 + 4];
            *(float4*)&b[0] = *(const float4*)&Bs[kk][tx * 8];
            *(float4*)&b[4] = *(const float4*)&Bs[kk][tx * 8 + 4];
#pragma unroll
            for (int i = 0; i < 8; i++)
#pragma unroll
                for (int j = 0; j < 8; j++)
                    acc[i][j] = fmaf(a[i], b[j], acc[i][j]);
        }
    }

#pragma unroll
    for (int i = 0; i < 8; i++) {
        const int m = bm + ty * 8 + i;
        float* zp = &g_z[(size_t)m * DH + bn + tx * 8];
        float4 o0, o1;
        const int n = bn + tx * 8;
        o0.x = fmaxf(acc[i][0] + benc[n + 0], 0.f);
        o0.y = fmaxf(acc[i][1] + benc[n + 1], 0.f);
        o0.z = fmaxf(acc[i][2] + benc[n + 2], 0.f);
        o0.w = fmaxf(acc[i][3] + benc[n + 3], 0.f);
        o1.x = fmaxf(acc[i][4] + benc[n + 4], 0.f);
        o1.y = fmaxf(acc[i][5] + benc[n + 5], 0.f);
        o1.z = fmaxf(acc[i][6] + benc[n + 6], 0.f);
        o1.w = fmaxf(acc[i][7] + benc[n + 7], 0.f);
        *(float4*)&zp[0] = o0;
        *(float4*)&zp[4] = o1;
    }
}

// ======================================================================
// Kernel 3: per-row top-NCAND candidates by fp32 (iterative argmax)
// ======================================================================
__device__ __forceinline__ void amax_merge(float& v, int& i, float ov, int oi) {
    if (ov > v || (ov == v && oi < i)) { v = ov; i = oi; }
}

__global__ __launch_bounds__(256)
void topk_kernel() {
    const int row = blockIdx.x;
    const int tid = threadIdx.x;
    float* zrow = &g_z[(size_t)row * DH];

    __shared__ float wv[8];
    __shared__ int   wi[8];
    __shared__ int   s_bi;

    float lv = -1.f; int li = INT_MAX;
    for (int j = 0; j < DH / 256; j++) {
        const int idx = tid + j * 256;
        const float x = zrow[idx];
        if (x > lv) { lv = x; li = idx; }
    }

    for (int it = 0; it < NCAND; it++) {
        float v = lv; int i = li;
#pragma unroll
        for (int off = 16; off > 0; off >>= 1) {
            const float ov = __shfl_down_sync(0xffffffffu, v, off);
            const int   oi = __shfl_down_sync(0xffffffffu, i, off);
            amax_merge(v, i, ov, oi);
        }
        if ((tid & 31) == 0) { wv[tid >> 5] = v; wi[tid >> 5] = i; }
        __syncthreads();
        if (tid < 32) {
            float v8 = (tid < 8) ? wv[tid] : -2.f;
            int   i8 = (tid < 8) ? wi[tid] : INT_MAX;
#pragma unroll
            for (int off = 4; off > 0; off >>= 1) {
                const float ov = __shfl_down_sync(0xffffffffu, v8, off);
                const int   oi = __shfl_down_sync(0xffffffffu, i8, off);
                amax_merge(v8, i8, ov, oi);
            }
            if (tid == 0) {
                s_bi = i8;
                g_candv[row * NCAND + it] = v8;
                g_candi[row * NCAND + it] = i8;
            }
        }
        __syncthreads();
        const int besti = s_bi;
        if ((besti & 255) == tid) {
            zrow[besti] = -1.f;
            lv = -1.f; li = INT_MAX;
#pragma unroll 8
            for (int j = 0; j < DH / 256; j++) {
                const int idx = tid + j * 256;
                const float x = zrow[idx];
                if (x > lv) { lv = x; li = idx; }
            }
        }
        __syncthreads();
    }
}

// ======================================================================
// Kernel 3b: fp64 refinement. Recompute the NCAND candidate dot products
// in double precision, rank by fp64 value (tie: lower index), keep true
// top-32 with their ORIGINAL fp32 z values, compacted in ascending index.
// One CTA (256 threads = 8 warps) per row.
// ======================================================================
__global__ __launch_bounds__(256)
void refine_kernel(const float* __restrict__ X, const float* __restrict__ W,
                   const float* __restrict__ benc) {
    const int row = blockIdx.x;
    const int tid = threadIdx.x;
    const int wid = tid >> 5;
    const int lid = tid & 31;

    __shared__ float  xs[DIN];
    __shared__ double dv[NCAND];
    __shared__ int    kept[NCAND];

    // stage x row
    for (int k = tid; k < DIN; k += 256) xs[k] = X[(size_t)row * DIN + k];
    __syncthreads();

    // fp64 dot per candidate (warp-per-candidate)
    for (int c = wid; c < NCAND; c += 8) {
        const int h = g_candi[row * NCAND + c];
        const float* w = &W[(size_t)h * DIN];
        double acc = 0.0;
#pragma unroll 6
        for (int k = lid; k < DIN; k += 32)
            acc = fma((double)xs[k], (double)w[k], acc);
#pragma unroll
        for (int off = 16; off > 0; off >>= 1)
            acc += __shfl_down_sync(0xffffffffu, acc, off);
        if (lid == 0) {
            acc += (double)benc[h];
            dv[c] = acc > 0.0 ? acc : 0.0;
        }
    }
    __syncthreads();

    // rank in fp64 (distinct values; ties broken by lower index)
    if (tid < NCAND) {
        const double vi = dv[tid];
        const int    ii = g_candi[row * NCAND + tid];
        int rank = 0;
        for (int j = 0; j < NCAND; j++) {
            const double vj = dv[j];
            const int    ij = g_candi[row * NCAND + j];
            rank += (vj > vi || (vj == vi && ij < ii)) ? 1 : 0;
        }
        kept[tid] = (rank < TK) ? 1 : 0;
    }
    __syncthreads();

    // compact kept candidates in ascending hidden-index order
    if (tid < NCAND && kept[tid]) {
        const int ii = g_candi[row * NCAND + tid];
        int slot = 0;
        for (int j = 0; j < NCAND; j++) {
            if (kept[j] && g_candi[row * NCAND + j] < ii) slot++;
        }
        g_selv[row * TK + slot] = g_candv[row * NCAND + tid];  // original fp32 z
        g_seli[row * TK + slot] = ii;
    }
}

// ======================================================================
// Kernel 4: sparse decode  out[b,:] = b_dec + sum_k v_k * WdT[idx_k, :]
// ascending-index accumulation, exact fp32.
// ======================================================================
__global__ __launch_bounds__(256)
void decode_kernel(const float* __restrict__ bdec, float* __restrict__ out) {
    const int row = blockIdx.x;
    const int tid = threadIdx.x;
    __shared__ float sv[TK];
    __shared__ int   si[TK];
    if (tid < TK) {
        sv[tid] = g_selv[row * TK + tid];
        si[tid] = g_seli[row * TK + tid];
    }
    __syncthreads();

    float acc0 = bdec[tid];
    float acc1 = bdec[tid + 256];
    float acc2 = bdec[tid + 512];
#pragma unroll 8
    for (int k = 0; k < TK; k++) {
        const float v = sv[k];
        const float* w = &g_wdt[(size_t)si[k] * DIN];
        acc0 = fmaf(v, w[tid],       acc0);
        acc1 = fmaf(v, w[tid + 256], acc1);
        acc2 = fmaf(v, w[tid + 512], acc2);
    }
    float* o = &out[(size_t)row * DIN];
    o[tid]       = acc0;
    o[tid + 256] = acc1;
    o[tid + 512] = acc2;
}

// ======================================================================
// launch
// ======================================================================
extern "C" void kernel_launch(void* const* d_in, const int* in_sizes, int n_in,
                              void* d_out, int out_size) {
    const float* x     = (const float*)d_in[0];   // [8192, 768]
    const float* w_enc = (const float*)d_in[1];   // [16384, 768]
    const float* b_enc = (const float*)d_in[2];   // [16384]
    const float* w_dec = (const float*)d_in[3];   // [768, 16384]
    const float* b_dec = (const float*)d_in[4];   // [768]
    float* out = (float*)d_out;                   // [8192, 768]

    {
        dim3 grid(DH / 32, DIN / 32);
        dim3 block(32, 8);
        transpose_wdec<<<grid, block>>>(w_dec);
    }
    {
        dim3 grid(DH / 128, BATCH / 128);
        encode_kernel<<<grid, 256>>>(x, w_enc, b_enc);
    }
    topk_kernel<<<BATCH, 256>>>();
    refine_kernel<<<BATCH, 256>>>(x, w_enc, b_enc);
    decode_kernel<<<BATCH, 256>>>(b_dec, out);
}

// round 5
// speedup vs baseline: 5.1797x; 5.1797x over previous
#include <cuda_runtime.h>
#include <cuda_bf16.h>
#include <cstdint>
#include <climits>

#define BATCH 8192
#define DIN   768
#define DH    16384
#define TK    32
#define CMAX  512
#define NBIN  2048
#define CUMTGT 48

// ---- scratch (static device globals; no dynamic allocation) ----
__device__ float g_z[(size_t)BATCH * DH];          // 512 MB post-relu activations (bf16-GEMM accuracy)
__device__ float g_wdt[(size_t)DH * DIN];          // 48 MB transposed W_dec
__device__ __nv_bfloat16 g_xbf[(size_t)BATCH * DIN];
__device__ __nv_bfloat16 g_wbf[(size_t)DH * DIN];
__device__ int   g_candi[(size_t)BATCH * CMAX];    // candidate indices per row
__device__ int   g_candcnt[BATCH];
__device__ float g_selv[BATCH * TK];               // final gating values
__device__ int   g_seli[BATCH * TK];

// ======================================================================
// helpers (all target-independent PTX: cp.async, ldmatrix, mma.sync)
// ======================================================================
__device__ __forceinline__ uint32_t smem_u32(const void* p) {
    uint32_t a;
    asm("{ .reg .u64 t; cvta.to.shared.u64 t, %1; cvt.u32.u64 %0, t; }" : "=r"(a) : "l"(p));
    return a;
}
__device__ __forceinline__ void cpa16(uint32_t dst, const void* src) {
    asm volatile("cp.async.cg.shared.global [%0], [%1], 16;" :: "r"(dst), "l"(src));
}
#define CP_COMMIT() asm volatile("cp.async.commit_group;" ::: "memory")
#define CP_WAIT(n)  asm volatile("cp.async.wait_group %0;" :: "n"(n) : "memory")

__device__ __forceinline__ void ldm_x4(uint32_t* r, uint32_t addr) {
    asm volatile("ldmatrix.sync.aligned.m8n8.x4.shared.b16 {%0,%1,%2,%3}, [%4];"
        : "=r"(r[0]), "=r"(r[1]), "=r"(r[2]), "=r"(r[3]) : "r"(addr));
}
__device__ __forceinline__ void mma16816(float* d, const uint32_t* a, uint32_t b0, uint32_t b1) {
    asm volatile(
        "mma.sync.aligned.m16n8k16.row.col.f32.bf16.bf16.f32 "
        "{%0,%1,%2,%3}, {%4,%5,%6,%7}, {%8,%9}, {%0,%1,%2,%3};"
        : "+f"(d[0]), "+f"(d[1]), "+f"(d[2]), "+f"(d[3])
        : "r"(a[0]), "r"(a[1]), "r"(a[2]), "r"(a[3]), "r"(b0), "r"(b1));
}

// ======================================================================
// Kernel 0: fp32 -> bf16 conversion (vectorized)
// ======================================================================
__global__ void cvt_bf16_kernel(const float* __restrict__ s, __nv_bfloat16* __restrict__ d, int n4) {
    const int i = blockIdx.x * 256 + threadIdx.x;
    if (i < n4) {
        const float4 v = ((const float4*)s)[i];
        ((__nv_bfloat162*)d)[i * 2 + 0] = __floats2bfloat162_rn(v.x, v.y);
        ((__nv_bfloat162*)d)[i * 2 + 1] = __floats2bfloat162_rn(v.z, v.w);
    }
}

// ======================================================================
// Kernel 1: transpose W_dec [DIN, DH] -> g_wdt [DH, DIN]  (fp32, exact)
// ======================================================================
__global__ void transpose_wdec(const float* __restrict__ wdec) {
    __shared__ float tile[32][33];
    const int h0 = blockIdx.x * 32;
    const int i0 = blockIdx.y * 32;
#pragma unroll
    for (int j = 0; j < 32; j += 8)
        tile[threadIdx.y + j][threadIdx.x] =
            wdec[(size_t)(i0 + threadIdx.y + j) * DH + (h0 + threadIdx.x)];
    __syncthreads();
#pragma unroll
    for (int j = 0; j < 32; j += 8)
        g_wdt[(size_t)(h0 + threadIdx.y + j) * DIN + (i0 + threadIdx.x)] =
            tile[threadIdx.x][threadIdx.y + j];
}

// ======================================================================
// Kernel 2: HMMA bf16 encode GEMM  z = relu(X @ W^T + b)
//   X bf16 [BATCH, DIN], W bf16 [DH, DIN], both K-contiguous.
//   BM=BN=128, BK=32, double-buffered cp.async, 80B-pitch rows (bank-conflict
//   free for ldmatrix: 8 rows at stride 80B cover all 32 banks).
//   8 warps in 4(m) x 2(n); warp tile 32x64; m16n8k16 bf16 -> f32.
// ======================================================================
#define EBK 32
#define PITCH 80      // 64B data + 16B pad per row
#define NKB (DIN / EBK)   // 24

__device__ __forceinline__ void enc_load(char* sA, char* sB,
                                         const __nv_bfloat16* __restrict__ X,
                                         const __nv_bfloat16* __restrict__ W,
                                         int bm, int bn, int kc, int tid) {
    const int k0 = kc * EBK;
#pragma unroll
    for (int i = 0; i < 2; i++) {
        const int cid = tid + i * 256;          // 512 chunks: 128 rows x 4 x 16B
        const int r = cid >> 2, c = cid & 3;
        cpa16(smem_u32(sA + r * PITCH + c * 16), &X[(size_t)(bm + r) * DIN + k0 + c * 8]);
        cpa16(smem_u32(sB + r * PITCH + c * 16), &W[(size_t)(bn + r) * DIN + k0 + c * 8]);
    }
    CP_COMMIT();
}

__global__ __launch_bounds__(256, 2)
void encode_mma(const __nv_bfloat16* __restrict__ X, const __nv_bfloat16* __restrict__ W,
                const float* __restrict__ benc) {
    __shared__ __align__(16) char sA[2][128 * PITCH];
    __shared__ __align__(16) char sB[2][128 * PITCH];
    __shared__ float sbias[128];

    const int tid = threadIdx.x;
    const int lane = tid & 31;
    const int wid = tid >> 5;
    const int warp_m = wid & 3;       // 4 warps along m
    const int warp_n = wid >> 2;      // 2 warps along n
    const int bm = blockIdx.y * 128;
    const int bn = blockIdx.x * 128;

    if (tid < 128) sbias[tid] = benc[bn + tid];

    float d[2][8][4];
#pragma unroll
    for (int mt = 0; mt < 2; mt++)
#pragma unroll
        for (int nt = 0; nt < 8; nt++)
#pragma unroll
            for (int q = 0; q < 4; q++) d[mt][nt][q] = 0.f;

    // ldmatrix source addresses (per warp, fixed row patterns)
    // A: row = warp_m*32 + mt*16 + (lane & 15); k-halfword byte = ((lane>>4)&1)*16
    const int a_row = warp_m * 32 + (lane & 15);
    const int a_kb  = ((lane >> 4) & 1) * 16;
    // B: n = warp_n*64 + p*16 + (lane&7) + ((lane>>4)<<3); k byte = ((lane>>3)&1)*16
    const int b_row = warp_n * 64 + (lane & 7) + ((lane >> 4) << 3);
    const int b_kb  = ((lane >> 3) & 1) * 16;

    enc_load(sA[0], sB[0], X, W, bm, bn, 0, tid);
    enc_load(sA[1], sB[1], X, W, bm, bn, 1, tid);

    for (int kb = 0; kb < NKB; kb++) {
        if (kb >= NKB - 2) CP_WAIT(0); else CP_WAIT(1);
        __syncthreads();
        char* cA = sA[kb & 1];
        char* cB = sB[kb & 1];

#pragma unroll
        for (int s = 0; s < 2; s++) {          // two k16 steps per 32-chunk
            uint32_t a[2][4], b[4][4];
#pragma unroll
            for (int mt = 0; mt < 2; mt++)
                ldm_x4(a[mt], smem_u32(cA + (a_row + mt * 16) * PITCH + s * 32 + a_kb));
#pragma unroll
            for (int p = 0; p < 4; p++)
                ldm_x4(b[p], smem_u32(cB + (b_row + p * 16) * PITCH + s * 32 + b_kb));
#pragma unroll
            for (int mt = 0; mt < 2; mt++)
#pragma unroll
                for (int p = 0; p < 4; p++) {
                    mma16816(d[mt][2 * p],     a[mt], b[p][0], b[p][1]);
                    mma16816(d[mt][2 * p + 1], a[mt], b[p][2], b[p][3]);
                }
        }
        __syncthreads();
        if (kb + 2 < NKB)
            enc_load(sA[kb & 1], sB[kb & 1], X, W, bm, bn, kb + 2, tid);
    }

    // epilogue: bias + relu + fp32 store
#pragma unroll
    for (int mt = 0; mt < 2; mt++) {
        const int r0 = bm + warp_m * 32 + mt * 16 + (lane >> 2);
#pragma unroll
        for (int nt = 0; nt < 8; nt++) {
            const int cl = warp_n * 64 + nt * 8 + (lane & 3) * 2;
            const float b0 = sbias[cl], b1 = sbias[cl + 1];
            float2 v0, v1;
            v0.x = fmaxf(d[mt][nt][0] + b0, 0.f);
            v0.y = fmaxf(d[mt][nt][1] + b1, 0.f);
            v1.x = fmaxf(d[mt][nt][2] + b0, 0.f);
            v1.y = fmaxf(d[mt][nt][3] + b1, 0.f);
            *(float2*)&g_z[(size_t)r0 * DH + bn + cl]       = v0;
            *(float2*)&g_z[(size_t)(r0 + 8) * DH + bn + cl] = v1;
        }
    }
}

// ======================================================================
// Kernel 3: histogram candidate select. One CTA per row.
// Keep all z whose float-bits >= cutoff bin where suffix count >= CUMTGT.
// ======================================================================
__global__ __launch_bounds__(256)
void hist_kernel() {
    const int row = blockIdx.x;
    const int tid = threadIdx.x;
    __shared__ uint32_t hist[NBIN];
    __shared__ uint32_t gsum[256];
    __shared__ uint32_t s_cut;
    __shared__ uint32_t s_cnt;

    for (int i = tid; i < NBIN; i += 256) hist[i] = 0;
    if (tid == 0) s_cnt = 0;
    __syncthreads();

    const float4* z4 = (const float4*)&g_z[(size_t)row * DH];
    float v[64];
#pragma unroll
    for (int j = 0; j < 16; j++) {
        const float4 t = z4[tid + j * 256];
        v[j * 4 + 0] = t.x; v[j * 4 + 1] = t.y; v[j * 4 + 2] = t.z; v[j * 4 + 3] = t.w;
    }
#pragma unroll
    for (int j = 0; j < 64; j++)
        if (v[j] > 0.f) atomicAdd(&hist[__float_as_uint(v[j]) >> 20], 1u);
    __syncthreads();

    uint32_t s = 0;
#pragma unroll
    for (int q = 0; q < 8; q++) s += hist[tid * 8 + q];
    gsum[tid] = s;
    __syncthreads();

    if (tid == 0) {
        uint32_t cum = 0; int g = 255;
        for (; g >= 0; --g) {
            if (cum + gsum[g] >= CUMTGT) break;
            cum += gsum[g];
        }
        uint32_t cut = 1;   // g < 0: take every positive value
        if (g >= 0) {
            int b = g * 8 + 7; uint32_t c2 = cum;
            for (; b > g * 8; --b) { c2 += hist[b]; if (c2 >= CUMTGT) break; }
            cut = ((uint32_t)b) << 20;
            if (cut == 0) cut = 1;
        }
        s_cut = cut;
    }
    __syncthreads();

    const uint32_t cut = s_cut;
#pragma unroll
    for (int j = 0; j < 64; j++) {
        if (v[j] > 0.f && __float_as_uint(v[j]) >= cut) {
            const int p = atomicAdd(&s_cnt, 1u);
            if (p < CMAX) {
                const int idx = (tid + (j >> 2) * 256) * 4 + (j & 3);
                g_candi[(size_t)row * CMAX + p] = idx;
            }
        }
    }
    __syncthreads();
    if (tid == 0) g_candcnt[row] = (s_cnt < CMAX) ? (int)s_cnt : CMAX;
}

// ======================================================================
// Kernel 4: compensated-fp32 (double-float, ~1e-11 rel) refinement.
// Recompute candidate dot products exactly enough to rank as fp64 truth;
// emit true top-32 with high-precision gating values.
// ======================================================================
__global__ __launch_bounds__(256)
void refine_kernel(const float* __restrict__ X, const float* __restrict__ W,
                   const float* __restrict__ benc) {
    const int row = blockIdx.x;
    const int tid = threadIdx.x;
    const int wid = tid >> 5;
    const int lid = tid & 31;

    __shared__ float  xs[DIN];
    __shared__ double dv[CMAX];
    __shared__ int    ci[CMAX];
    __shared__ int    kept[CMAX];

    const int cnt = g_candcnt[row];
    for (int k = tid; k < DIN; k += 256) xs[k] = X[(size_t)row * DIN + k];
    for (int c = tid; c < cnt; c += 256) ci[c] = g_candi[(size_t)row * CMAX + c];
    if (tid < TK) { g_selv[row * TK + tid] = 0.f; g_seli[row * TK + tid] = 0; }
    __syncthreads();

    for (int c = wid; c < cnt; c += 8) {
        const int h = ci[c];
        const float* w = &W[(size_t)h * DIN];
        float hi = 0.f, lo = 0.f;
#pragma unroll 4
        for (int k = lid; k < DIN; k += 32) {
            const float a = xs[k], b = w[k];
            const float p = a * b;
            const float e = fmaf(a, b, -p);      // exact product error
            const float t = hi + p;              // TwoSum(hi, p)
            const float bb = t - hi;
            const float err = (hi - (t - bb)) + (p - bb);
            hi = t;
            lo += e + err;
        }
        // warp reduce (hi,lo) with compensated merges
#pragma unroll
        for (int off = 16; off > 0; off >>= 1) {
            const float oh = __shfl_down_sync(0xffffffffu, hi, off);
            const float ol = __shfl_down_sync(0xffffffffu, lo, off);
            const float t = hi + oh;
            const float bb = t - hi;
            const float err = (hi - (t - bb)) + (oh - bb);
            hi = t;
            lo += ol + err;
        }
        if (lid == 0) {
            const float be = benc[h];
            const float t = hi + be;
            const float bb = t - hi;
            const float err = (hi - (t - bb)) + (be - bb);
            double acc = (double)t + (double)(lo + err);
            dv[c] = acc > 0.0 ? acc : 0.0;
        }
    }
    __syncthreads();

    // exact rank (ties by lower index)
    for (int c = tid; c < cnt; c += 256) {
        const double vi = dv[c]; const int ii = ci[c];
        int rank = 0;
        for (int j = 0; j < cnt; j++) {
            const double vj = dv[j];
            rank += (vj > vi || (vj == vi && ci[j] < ii)) ? 1 : 0;
        }
        kept[c] = (rank < TK) ? 1 : 0;
    }
    __syncthreads();

    // compact kept in ascending hidden-index order
    for (int c = tid; c < cnt; c += 256) {
        if (kept[c]) {
            const int ii = ci[c];
            int slot = 0;
            for (int j = 0; j < cnt; j++)
                if (kept[j] && ci[j] < ii) slot++;
            if (slot < TK) {
                g_selv[row * TK + slot] = (float)dv[c];
                g_seli[row * TK + slot] = ii;
            }
        }
    }
}

// ======================================================================
// Kernel 5: sparse decode  out[b,:] = b_dec + sum_k v_k * WdT[idx_k, :]
// ======================================================================
__global__ __launch_bounds__(256)
void decode_kernel(const float* __restrict__ bdec, float* __restrict__ out) {
    const int row = blockIdx.x;
    const int tid = threadIdx.x;
    __shared__ float sv[TK];
    __shared__ int   si[TK];
    if (tid < TK) {
        sv[tid] = g_selv[row * TK + tid];
        si[tid] = g_seli[row * TK + tid];
    }
    __syncthreads();

    float acc0 = bdec[tid];
    float acc1 = bdec[tid + 256];
    float acc2 = bdec[tid + 512];
#pragma unroll 8
    for (int k = 0; k < TK; k++) {
        const float vv = sv[k];
        const float* w = &g_wdt[(size_t)si[k] * DIN];
        acc0 = fmaf(vv, w[tid],       acc0);
        acc1 = fmaf(vv, w[tid + 256], acc1);
        acc2 = fmaf(vv, w[tid + 512], acc2);
    }
    float* o = &out[(size_t)row * DIN];
    o[tid]       = acc0;
    o[tid + 256] = acc1;
    o[tid + 512] = acc2;
}

// ======================================================================
// launch
// ======================================================================
extern "C" void kernel_launch(void* const* d_in, const int* in_sizes, int n_in,
                              void* d_out, int out_size) {
    const float* x     = (const float*)d_in[0];   // [8192, 768]
    const float* w_enc = (const float*)d_in[1];   // [16384, 768]
    const float* b_enc = (const float*)d_in[2];   // [16384]
    const float* w_dec = (const float*)d_in[3];   // [768, 16384]
    const float* b_dec = (const float*)d_in[4];   // [768]
    float* out = (float*)d_out;                   // [8192, 768]

    // 0. bf16 copies of X, W_enc
    __nv_bfloat16* xbf; cudaGetSymbolAddress((void**)&xbf, g_xbf);
    __nv_bfloat16* wbf; cudaGetSymbolAddress((void**)&wbf, g_wbf);
    {
        const int n4x = BATCH * DIN / 4;
        cvt_bf16_kernel<<<(n4x + 255) / 256, 256>>>(x, xbf, n4x);
        const int n4w = DH * DIN / 4;
        cvt_bf16_kernel<<<(n4w + 255) / 256, 256>>>(w_enc, wbf, n4w);
    }
    // 1. transpose W_dec for coalesced decode gathers
    {
        dim3 grid(DH / 32, DIN / 32);
        dim3 block(32, 8);
        transpose_wdec<<<grid, block>>>(w_dec);
    }
    // 2. HMMA bf16 encode GEMM + bias + relu
    {
        dim3 grid(DH / 128, BATCH / 128);
        encode_mma<<<grid, 256>>>(xbf, wbf, b_enc);
    }
    // 3. per-row candidate capture (histogram select)
    hist_kernel<<<BATCH, 256>>>();
    // 4. compensated-precision exact top-32
    refine_kernel<<<BATCH, 256>>>(x, w_enc, b_enc);
    // 5. sparse decode
    decode_kernel<<<BATCH, 256>>>(b_dec, out);
}

// round 7
// speedup vs baseline: 5.5549x; 1.0724x over previous
#include <cuda_runtime.h>
#include <cuda_bf16.h>
#include <cstdint>
#include <climits>

#define BATCH 8192
#define DIN   768
#define DH    16384
#define TK    32
#define CMAX  512
#define NBIN  8192          // bf16-bits >> 2
#define CUMTGT 48

// ---- scratch (static device globals; no dynamic allocation) ----
__device__ __nv_bfloat16 g_zb[(size_t)BATCH * DH];   // 256 MB post-relu activations (bf16)
__device__ float g_wdt[(size_t)DH * DIN];            // 48 MB transposed W_dec
__device__ __nv_bfloat16 g_xbf[(size_t)BATCH * DIN];
__device__ __nv_bfloat16 g_wbf[(size_t)DH * DIN];
__device__ int   g_candi[(size_t)BATCH * CMAX];
__device__ int   g_candcnt[BATCH];
__device__ float g_selv[BATCH * TK];
__device__ int   g_seli[BATCH * TK];

// ======================================================================
// helpers (all target-independent PTX: cp.async, ldmatrix, mma.sync)
// ======================================================================
__device__ __forceinline__ uint32_t smem_u32(const void* p) {
    uint32_t a;
    asm("{ .reg .u64 t; cvta.to.shared.u64 t, %1; cvt.u32.u64 %0, t; }" : "=r"(a) : "l"(p));
    return a;
}
__device__ __forceinline__ void cpa16(uint32_t dst, const void* src) {
    asm volatile("cp.async.cg.shared.global [%0], [%1], 16;" :: "r"(dst), "l"(src));
}
#define CP_COMMIT() asm volatile("cp.async.commit_group;" ::: "memory")
#define CP_WAIT(n)  asm volatile("cp.async.wait_group %0;" :: "n"(n) : "memory")

__device__ __forceinline__ void ldm_x4(uint32_t* r, uint32_t addr) {
    asm volatile("ldmatrix.sync.aligned.m8n8.x4.shared.b16 {%0,%1,%2,%3}, [%4];"
        : "=r"(r[0]), "=r"(r[1]), "=r"(r[2]), "=r"(r[3]) : "r"(addr));
}
__device__ __forceinline__ void mma16816(float* d, const uint32_t* a, uint32_t b0, uint32_t b1) {
    asm volatile(
        "mma.sync.aligned.m16n8k16.row.col.f32.bf16.bf16.f32 "
        "{%0,%1,%2,%3}, {%4,%5,%6,%7}, {%8,%9}, {%0,%1,%2,%3};"
        : "+f"(d[0]), "+f"(d[1]), "+f"(d[2]), "+f"(d[3])
        : "r"(a[0]), "r"(a[1]), "r"(a[2]), "r"(a[3]), "r"(b0), "r"(b1));
}

// ======================================================================
// Kernel 0: fp32 -> bf16 conversion (vectorized)
// ======================================================================
__global__ void cvt_bf16_kernel(const float* __restrict__ s, __nv_bfloat16* __restrict__ d, int n4) {
    const int i = blockIdx.x * 256 + threadIdx.x;
    if (i < n4) {
        const float4 v = ((const float4*)s)[i];
        ((__nv_bfloat162*)d)[i * 2 + 0] = __floats2bfloat162_rn(v.x, v.y);
        ((__nv_bfloat162*)d)[i * 2 + 1] = __floats2bfloat162_rn(v.z, v.w);
    }
}

// ======================================================================
// Kernel 1: transpose W_dec [DIN, DH] -> g_wdt [DH, DIN]  (fp32, exact)
// ======================================================================
__global__ void transpose_wdec(const float* __restrict__ wdec) {
    __shared__ float tile[32][33];
    const int h0 = blockIdx.x * 32;
    const int i0 = blockIdx.y * 32;
#pragma unroll
    for (int j = 0; j < 32; j += 8)
        tile[threadIdx.y + j][threadIdx.x] =
            wdec[(size_t)(i0 + threadIdx.y + j) * DH + (h0 + threadIdx.x)];
    __syncthreads();
#pragma unroll
    for (int j = 0; j < 32; j += 8)
        g_wdt[(size_t)(h0 + threadIdx.y + j) * DIN + (i0 + threadIdx.x)] =
            tile[threadIdx.x][threadIdx.y + j];
}

// ======================================================================
// Kernel 2: HMMA bf16 encode GEMM  z = relu(X @ W^T + b) -> bf16
//   BM=BN=128, BK=32, 3-stage cp.async pipeline, one sync per k-iter.
//   80B-pitch rows (bank-conflict-free ldmatrix). 8 warps 4(m) x 2(n),
//   warp tile 32x64, m16n8k16 bf16 -> f32 accum.
// ======================================================================
#define EBK 32
#define PITCH 80
#define NKB (DIN / EBK)       // 24
#define STG_BYTES (128 * PITCH)          // 10240 per tile
#define STAGE_BYTES (2 * STG_BYTES)      // A + B = 20480
#define ENC_SMEM (3 * STAGE_BYTES + 512) // 61952

__device__ __forceinline__ void enc_load(char* sA, char* sB,
                                         const __nv_bfloat16* __restrict__ X,
                                         const __nv_bfloat16* __restrict__ W,
                                         int bm, int bn, int kc, int tid) {
    const int k0 = kc * EBK;
#pragma unroll
    for (int i = 0; i < 2; i++) {
        const int cid = tid + i * 256;          // 512 chunks: 128 rows x 4 x 16B
        const int r = cid >> 2, c = cid & 3;
        cpa16(smem_u32(sA + r * PITCH + c * 16), &X[(size_t)(bm + r) * DIN + k0 + c * 8]);
        cpa16(smem_u32(sB + r * PITCH + c * 16), &W[(size_t)(bn + r) * DIN + k0 + c * 8]);
    }
    CP_COMMIT();
}

__global__ __launch_bounds__(256, 2)
void encode_mma(const __nv_bfloat16* __restrict__ X, const __nv_bfloat16* __restrict__ W,
                const float* __restrict__ benc) {
    extern __shared__ __align__(16) char smem[];
    float* sbias = (float*)(smem + 3 * STAGE_BYTES);

    const int tid = threadIdx.x;
    const int lane = tid & 31;
    const int wid = tid >> 5;
    const int warp_m = wid & 3;
    const int warp_n = wid >> 2;
    const int bm = blockIdx.y * 128;
    const int bn = blockIdx.x * 128;

    if (tid < 128) sbias[tid] = benc[bn + tid];

    float d[2][8][4];
#pragma unroll
    for (int mt = 0; mt < 2; mt++)
#pragma unroll
        for (int nt = 0; nt < 8; nt++)
#pragma unroll
            for (int q = 0; q < 4; q++) d[mt][nt][q] = 0.f;

    const int a_row = warp_m * 32 + (lane & 15);
    const int a_kb  = ((lane >> 4) & 1) * 16;
    const int b_row = warp_n * 64 + (lane & 7) + ((lane >> 4) << 3);
    const int b_kb  = ((lane >> 3) & 1) * 16;

    enc_load(smem + 0 * STAGE_BYTES, smem + 0 * STAGE_BYTES + STG_BYTES, X, W, bm, bn, 0, tid);
    enc_load(smem + 1 * STAGE_BYTES, smem + 1 * STAGE_BYTES + STG_BYTES, X, W, bm, bn, 1, tid);

    int cur = 0, nxt2 = 2;
    for (int kb = 0; kb < NKB; kb++) {
        if (kb >= NKB - 1) CP_WAIT(0); else CP_WAIT(1);
        __syncthreads();   // stage kb data visible; stage (kb+2)%3 free for reuse

        if (kb + 2 < NKB) {
            char* base = smem + nxt2 * STAGE_BYTES;
            enc_load(base, base + STG_BYTES, X, W, bm, bn, kb + 2, tid);
        }

        char* cA = smem + cur * STAGE_BYTES;
        char* cB = cA + STG_BYTES;
#pragma unroll
        for (int s = 0; s < 2; s++) {          // two k16 steps per 32-chunk
            uint32_t a[2][4], b[4][4];
#pragma unroll
            for (int mt = 0; mt < 2; mt++)
                ldm_x4(a[mt], smem_u32(cA + (a_row + mt * 16) * PITCH + s * 32 + a_kb));
#pragma unroll
            for (int p = 0; p < 4; p++)
                ldm_x4(b[p], smem_u32(cB + (b_row + p * 16) * PITCH + s * 32 + b_kb));
#pragma unroll
            for (int mt = 0; mt < 2; mt++)
#pragma unroll
                for (int p = 0; p < 4; p++) {
                    mma16816(d[mt][2 * p],     a[mt], b[p][0], b[p][1]);
                    mma16816(d[mt][2 * p + 1], a[mt], b[p][2], b[p][3]);
                }
        }
        cur = (cur + 1) % 3;
        nxt2 = (nxt2 + 1) % 3;
    }

    // epilogue: bias + relu + bf16 store
#pragma unroll
    for (int mt = 0; mt < 2; mt++) {
        const int r0 = bm + warp_m * 32 + mt * 16 + (lane >> 2);
#pragma unroll
        for (int nt = 0; nt < 8; nt++) {
            const int cl = warp_n * 64 + nt * 8 + (lane & 3) * 2;
            const float b0 = sbias[cl], b1 = sbias[cl + 1];
            const __nv_bfloat162 v0 = __floats2bfloat162_rn(
                fmaxf(d[mt][nt][0] + b0, 0.f), fmaxf(d[mt][nt][1] + b1, 0.f));
            const __nv_bfloat162 v1 = __floats2bfloat162_rn(
                fmaxf(d[mt][nt][2] + b0, 0.f), fmaxf(d[mt][nt][3] + b1, 0.f));
            *(__nv_bfloat162*)&g_zb[(size_t)r0 * DH + bn + cl]       = v0;
            *(__nv_bfloat162*)&g_zb[(size_t)(r0 + 8) * DH + bn + cl] = v1;
        }
    }
}

// ======================================================================
// Kernel 3: histogram candidate select on bf16 z. One CTA per row.
// Row = 16384 bf16 = 2048 uint4; each thread owns 8 coalesced uint4
// (32 uint32 = 64 bf16 values). Bin = bf16-bits >> 2.
// bf16 element index of word w in uint4 u: u*8 + w*2 (+1 for high half).
// ======================================================================
__global__ __launch_bounds__(256)
void hist_kernel() {
    const int row = blockIdx.x;
    const int tid = threadIdx.x;
    __shared__ uint32_t hist[NBIN];
    __shared__ uint32_t gsum[256];
    __shared__ uint32_t s_cut;
    __shared__ uint32_t s_cnt;

    for (int i = tid; i < NBIN; i += 256) hist[i] = 0;
    if (tid == 0) s_cnt = 0;
    __syncthreads();

    const uint4* z4 = (const uint4*)&g_zb[(size_t)row * DH];
    uint32_t v[32];
#pragma unroll
    for (int j = 0; j < 8; j++) {
        const uint4 t = z4[tid + j * 256];
        v[j * 4 + 0] = t.x; v[j * 4 + 1] = t.y; v[j * 4 + 2] = t.z; v[j * 4 + 3] = t.w;
    }
#pragma unroll
    for (int j = 0; j < 32; j++) {
        const uint32_t lo = v[j] & 0xffffu;
        const uint32_t hi = v[j] >> 16;
        if (lo && lo < 0x8000u) atomicAdd(&hist[lo >> 2], 1u);
        if (hi && hi < 0x8000u) atomicAdd(&hist[hi >> 2], 1u);
    }
    __syncthreads();

    uint32_t s = 0;
#pragma unroll
    for (int q = 0; q < NBIN / 256; q++) s += hist[tid * (NBIN / 256) + q];
    gsum[tid] = s;
    __syncthreads();

    if (tid == 0) {
        uint32_t cum = 0; int g = 255;
        for (; g >= 0; --g) {
            if (cum + gsum[g] >= CUMTGT) break;
            cum += gsum[g];
        }
        uint32_t cut = 1;   // g < 0: take every positive value
        if (g >= 0) {
            const int gb = NBIN / 256;
            int b = g * gb + gb - 1; uint32_t c2 = cum;
            for (; b > g * gb; --b) { c2 += hist[b]; if (c2 >= CUMTGT) break; }
            cut = ((uint32_t)b) << 2;
            if (cut == 0) cut = 1;
        }
        s_cut = cut;
    }
    __syncthreads();

    const uint32_t cut = s_cut;
#pragma unroll
    for (int j = 0; j < 32; j++) {
        const int u = tid + (j >> 2) * 256;     // uint4 index within row
        const int base = u * 8 + (j & 3) * 2;   // bf16 element index
        const uint32_t lo = v[j] & 0xffffu;
        const uint32_t hi = v[j] >> 16;
        if (lo < 0x8000u && lo >= cut) {
            const int p = atomicAdd(&s_cnt, 1u);
            if (p < CMAX) g_candi[(size_t)row * CMAX + p] = base;
        }
        if (hi < 0x8000u && hi >= cut) {
            const int p = atomicAdd(&s_cnt, 1u);
            if (p < CMAX) g_candi[(size_t)row * CMAX + p] = base + 1;
        }
    }
    __syncthreads();
    if (tid == 0) g_candcnt[row] = (s_cnt < CMAX) ? (int)s_cnt : CMAX;
}

// ======================================================================
// Kernel 4: compensated-fp32 (double-float, ~1e-11 rel) refinement.
// ======================================================================
__global__ __launch_bounds__(256)
void refine_kernel(const float* __restrict__ X, const float* __restrict__ W,
                   const float* __restrict__ benc) {
    const int row = blockIdx.x;
    const int tid = threadIdx.x;
    const int wid = tid >> 5;
    const int lid = tid & 31;

    __shared__ float  xs[DIN];
    __shared__ double dv[CMAX];
    __shared__ int    ci[CMAX];
    __shared__ int    kept[CMAX];

    const int cnt = g_candcnt[row];
    for (int k = tid; k < DIN; k += 256) xs[k] = X[(size_t)row * DIN + k];
    for (int c = tid; c < cnt; c += 256) ci[c] = g_candi[(size_t)row * CMAX + c];
    if (tid < TK) { g_selv[row * TK + tid] = 0.f; g_seli[row * TK + tid] = 0; }
    __syncthreads();

    for (int c = wid; c < cnt; c += 8) {
        const int h = ci[c];
        const float* w = &W[(size_t)h * DIN];
        float hi = 0.f, lo = 0.f;
#pragma unroll 4
        for (int k = lid; k < DIN; k += 32) {
            const float a = xs[k], b = w[k];
            const float p = a * b;
            const float e = fmaf(a, b, -p);
            const float t = hi + p;
            const float bb = t - hi;
            const float err = (hi - (t - bb)) + (p - bb);
            hi = t;
            lo += e + err;
        }
#pragma unroll
        for (int off = 16; off > 0; off >>= 1) {
            const float oh = __shfl_down_sync(0xffffffffu, hi, off);
            const float ol = __shfl_down_sync(0xffffffffu, lo, off);
            const float t = hi + oh;
            const float bb = t - hi;
            const float err = (hi - (t - bb)) + (oh - bb);
            hi = t;
            lo += ol + err;
        }
        if (lid == 0) {
            const float be = benc[h];
            const float t = hi + be;
            const float bb = t - hi;
            const float err = (hi - (t - bb)) + (be - bb);
            double acc = (double)t + (double)(lo + err);
            dv[c] = acc > 0.0 ? acc : 0.0;
        }
    }
    __syncthreads();

    for (int c = tid; c < cnt; c += 256) {
        const double vi = dv[c]; const int ii = ci[c];
        int rank = 0;
        for (int j = 0; j < cnt; j++) {
            const double vj = dv[j];
            rank += (vj > vi || (vj == vi && ci[j] < ii)) ? 1 : 0;
        }
        kept[c] = (rank < TK) ? 1 : 0;
    }
    __syncthreads();

    for (int c = tid; c < cnt; c += 256) {
        if (kept[c]) {
            const int ii = ci[c];
            int slot = 0;
            for (int j = 0; j < cnt; j++)
                if (kept[j] && ci[j] < ii) slot++;
            if (slot < TK) {
                g_selv[row * TK + slot] = (float)dv[c];
                g_seli[row * TK + slot] = ii;
            }
        }
    }
}

// ======================================================================
// Kernel 5: sparse decode  out[b,:] = b_dec + sum_k v_k * WdT[idx_k, :]
// ======================================================================
__global__ __launch_bounds__(256)
void decode_kernel(const float* __restrict__ bdec, float* __restrict__ out) {
    const int row = blockIdx.x;
    const int tid = threadIdx.x;
    __shared__ float sv[TK];
    __shared__ int   si[TK];
    if (tid < TK) {
        sv[tid] = g_selv[row * TK + tid];
        si[tid] = g_seli[row * TK + tid];
    }
    __syncthreads();

    float acc0 = bdec[tid];
    float acc1 = bdec[tid + 256];
    float acc2 = bdec[tid + 512];
#pragma unroll 8
    for (int k = 0; k < TK; k++) {
        const float vv = sv[k];
        const float* w = &g_wdt[(size_t)si[k] * DIN];
        acc0 = fmaf(vv, w[tid],       acc0);
        acc1 = fmaf(vv, w[tid + 256], acc1);
        acc2 = fmaf(vv, w[tid + 512], acc2);
    }
    float* o = &out[(size_t)row * DIN];
    o[tid]       = acc0;
    o[tid + 256] = acc1;
    o[tid + 512] = acc2;
}

// ======================================================================
// launch
// ======================================================================
extern "C" void kernel_launch(void* const* d_in, const int* in_sizes, int n_in,
                              void* d_out, int out_size) {
    const float* x     = (const float*)d_in[0];   // [8192, 768]
    const float* w_enc = (const float*)d_in[1];   // [16384, 768]
    const float* b_enc = (const float*)d_in[2];   // [16384]
    const float* w_dec = (const float*)d_in[3];   // [768, 16384]
    const float* b_dec = (const float*)d_in[4];   // [768]
    float* out = (float*)d_out;                   // [8192, 768]

    static int enc_attr_set = 0;
    if (!enc_attr_set) {
        cudaFuncSetAttribute(encode_mma, cudaFuncAttributeMaxDynamicSharedMemorySize, ENC_SMEM);
        enc_attr_set = 1;
    }

    // 0. bf16 copies of X, W_enc
    __nv_bfloat16* xbf; cudaGetSymbolAddress((void**)&xbf, g_xbf);
    __nv_bfloat16* wbf; cudaGetSymbolAddress((void**)&wbf, g_wbf);
    {
        const int n4x = BATCH * DIN / 4;
        cvt_bf16_kernel<<<(n4x + 255) / 256, 256>>>(x, xbf, n4x);
        const int n4w = DH * DIN / 4;
        cvt_bf16_kernel<<<(n4w + 255) / 256, 256>>>(w_enc, wbf, n4w);
    }
    // 1. transpose W_dec for coalesced decode gathers
    {
        dim3 grid(DH / 32, DIN / 32);
        dim3 block(32, 8);
        transpose_wdec<<<grid, block>>>(w_dec);
    }
    // 2. HMMA bf16 encode GEMM + bias + relu (3-stage pipeline)
    {
        dim3 grid(DH / 128, BATCH / 128);
        encode_mma<<<grid, 256, ENC_SMEM>>>(xbf, wbf, b_enc);
    }
    // 3. per-row candidate capture (fine-binned histogram)
    hist_kernel<<<BATCH, 256>>>();
    // 4. compensated-precision exact top-32
    refine_kernel<<<BATCH, 256>>>(x, w_enc, b_enc);
    // 5. sparse decode
    decode_kernel<<<BATCH, 256>>>(b_dec, out);
}